// round 17
// baseline (speedup 1.0000x reference)
#include <cuda_runtime.h>
#include <cuda_bf16.h>

#define THREADS 256

// Pair-reduce: lanes with (lane & s)==0 end with full reduction of `a`,
// lanes with (lane & s)!=0 end with full reduction of `b`.
__device__ __forceinline__ float pair_reduce(float a, float b, int s, int lane) {
    bool hi = (lane & s) != 0;
    float send = hi ? a : b;
    float recv = __shfl_xor_sync(0xffffffffu, send, s);
    float keep = hi ? b : a;
    return keep + recv;
}

__device__ __forceinline__ float4 fuse4(float4 a0, float4 a1, float4 a2, float4 a3,
                                        float w0, float w1, float w2, float w3) {
    float4 f;
    f.x = fmaf(a3.x, w3, fmaf(a2.x, w2, fmaf(a1.x, w1, a0.x * w0)));
    f.y = fmaf(a3.y, w3, fmaf(a2.y, w2, fmaf(a1.y, w1, a0.y * w0)));
    f.z = fmaf(a3.z, w3, fmaf(a2.z, w2, fmaf(a1.z, w1, a0.z * w0)));
    f.w = fmaf(a3.w, w3, fmaf(a2.w, w2, fmaf(a1.w, w1, a0.w * w0)));
    return f;
}

__global__ __launch_bounds__(THREADS, 4) void snn_fused_kernel(
    const float* __restrict__ x,       // [B,T,A,D] = [B,90,4,256]
    const float* __restrict__ w_ant,   // [4]
    const float* __restrict__ b_ant,   // scalar
    const float* __restrict__ w_hid,   // [10,256]
    const float* __restrict__ b_hid,   // [10]
    const float* __restrict__ w_time,  // [90]
    const float* __restrict__ b_time,  // scalar
    const float* __restrict__ w_out,   // [2,10]
    const float* __restrict__ b_out,   // [2]
    float* __restrict__ out,           // [B,2]
    int B)
{
    __shared__ float4 s_whid4[10 * 64];    // w_hid as float4: [h][64]
    __shared__ float  s_sn[2][90][10];     // double-buffered sn_in
    __shared__ float  s_wtime[90];
    __shared__ float  s_bias[10];

    const int tid  = threadIdx.x;
    const int warp = tid >> 5;
    const int lane = tid & 31;

    // ---- one-time init: stage weights into smem ----
    const float4* wh4 = reinterpret_cast<const float4*>(w_hid);
    for (int i = tid; i < 640; i += THREADS) s_whid4[i] = wh4[i];
    if (tid < 90) s_wtime[tid] = w_time[tid];
    __syncthreads();
    if (tid < 10) {
        const float* row = reinterpret_cast<const float*>(&s_whid4[tid * 64]);
        float s = 0.f;
        #pragma unroll 8
        for (int d = 0; d < 256; ++d) s += row[d];
        s_bias[tid] = b_hid[tid] + b_ant[0] * s;   // fold conv bias into hidden bias
    }
    const float wa0 = w_ant[0], wa1 = w_ant[1], wa2 = w_ant[2], wa3 = w_ant[3];
    __syncthreads();

    // loop-invariant per-lane reduction metadata
    const int h_mine = (lane & 2) ? (8 + ((lane >> 4) & 1))
                                  : (((lane >> 2) & 1) * 4 + ((lane >> 3) & 1) * 2 + ((lane >> 4) & 1));
    const bool writer = ((lane & 1) == 0) && (((lane & 2) == 0) || ((lane & 12) == 0));
    const float4* wl0 = s_whid4 + lane;   // per-lane weight base (half1 uses +32)

    // warp-reduce 10 partials; writer lane stores to s_sn[buf][t]
    auto reduce_store = [&](float acc[10], int t, int buf) {
        float v0 = pair_reduce(acc[0], acc[1], 16, lane);
        float v1 = pair_reduce(acc[2], acc[3], 16, lane);
        float v2 = pair_reduce(acc[4], acc[5], 16, lane);
        float v3 = pair_reduce(acc[6], acc[7], 16, lane);
        float v4 = pair_reduce(acc[8], acc[9], 16, lane);
        float u0 = pair_reduce(v0, v1, 8, lane);
        float u1 = pair_reduce(v2, v3, 8, lane);
        v4 += __shfl_xor_sync(0xffffffffu, v4, 8);
        float w0r = pair_reduce(u0, u1, 4, lane);
        v4 += __shfl_xor_sync(0xffffffffu, v4, 4);
        float z = pair_reduce(w0r, v4, 2, lane);
        z += __shfl_xor_sync(0xffffffffu, z, 1);
        if (writer) s_sn[buf][t][h_mine] = z;
    };

    // produce one timestep PAIR (t0, t0+1) into s_sn[buf]
    auto produce_pair = [&](const float4* xb, int t0, int buf) {
        const float4* xw0 = xb + t0 * 256 + lane;
        const float4* xw1 = xw0 + 256;
        float acc0[10], acc1[10];

        // ---- half 0 of BOTH timesteps: 8 LDG.128 in flight ----
        {
            float4 a0 = __ldcs(xw0      );
            float4 a1 = __ldcs(xw0 + 64 );
            float4 a2 = __ldcs(xw0 + 128);
            float4 a3 = __ldcs(xw0 + 192);
            float4 c0 = __ldcs(xw1      );
            float4 c1 = __ldcs(xw1 + 64 );
            float4 c2 = __ldcs(xw1 + 128);
            float4 c3 = __ldcs(xw1 + 192);
            float4 f = fuse4(a0, a1, a2, a3, wa0, wa1, wa2, wa3);
            float4 g = fuse4(c0, c1, c2, c3, wa0, wa1, wa2, wa3);
            #pragma unroll
            for (int h = 0; h < 10; ++h) {
                float4 w = wl0[h * 64];            // shared by both t's
                float r0, r1;
                r0 = f.x * w.x;
                r1 = g.x * w.x;
                r0 = fmaf(f.y, w.y, r0);
                r1 = fmaf(g.y, w.y, r1);
                r0 = fmaf(f.z, w.z, r0);
                r1 = fmaf(g.z, w.z, r1);
                r0 = fmaf(f.w, w.w, r0);
                r1 = fmaf(g.w, w.w, r1);
                acc0[h] = r0;
                acc1[h] = r1;
            }
        }

        // ---- half 1 of BOTH timesteps ----
        {
            float4 a0 = __ldcs(xw0 + 32 );
            float4 a1 = __ldcs(xw0 + 96 );
            float4 a2 = __ldcs(xw0 + 160);
            float4 a3 = __ldcs(xw0 + 224);
            float4 c0 = __ldcs(xw1 + 32 );
            float4 c1 = __ldcs(xw1 + 96 );
            float4 c2 = __ldcs(xw1 + 160);
            float4 c3 = __ldcs(xw1 + 224);
            float4 f = fuse4(a0, a1, a2, a3, wa0, wa1, wa2, wa3);
            float4 g = fuse4(c0, c1, c2, c3, wa0, wa1, wa2, wa3);
            #pragma unroll
            for (int h = 0; h < 10; ++h) {
                float4 w = wl0[h * 64 + 32];       // shared by both t's
                float r0 = acc0[h], r1 = acc1[h];
                r0 = fmaf(f.x, w.x, r0);
                r1 = fmaf(g.x, w.x, r1);
                r0 = fmaf(f.y, w.y, r0);
                r1 = fmaf(g.y, w.y, r1);
                r0 = fmaf(f.z, w.z, r0);
                r1 = fmaf(g.z, w.z, r1);
                r0 = fmaf(f.w, w.w, r0);
                r1 = fmaf(g.w, w.w, r1);
                acc0[h] = r0;
                acc1[h] = r1;
            }
        }

        reduce_store(acc0, t0,     buf);
        reduce_store(acc1, t0 + 1, buf);
    };

    // scan + output for one row (warp 7; lanes < 10 active in the recurrence)
    auto scan_row = [&](int b, int buf) {
        float fused = 0.f;
        if (lane < 10) {
            const int h = lane;
            const float bias = s_bias[h];
            float mem = 0.f, acc = 0.f;
            #pragma unroll 6
            for (int t = 0; t < 90; ++t) {
                float inp = s_sn[buf][t][h] + bias;
                // reset from PREVIOUS mem, reset_mechanism='zero'
                float mem_new = (mem > 1.0f) ? 0.0f : fmaf(0.95f, mem, inp);
                if (mem_new > 1.0f) acc += s_wtime[t];   // spike
                mem = mem_new;
            }
            fused = acc + b_time[0];
        }
        float c0 = (lane < 10) ? fused * __ldg(w_out + lane)      : 0.f;
        float c1 = (lane < 10) ? fused * __ldg(w_out + 10 + lane) : 0.f;
        #pragma unroll
        for (int s = 16; s > 0; s >>= 1) {
            c0 += __shfl_xor_sync(0xffffffffu, c0, s);
            c1 += __shfl_xor_sync(0xffffffffu, c1, s);
        }
        if (lane == 0) {
            float o0 = c0 + b_out[0];
            float o1 = c1 + b_out[1];
            float m  = fmaxf(o0, o1);
            float e0 = __expf(o0 - m);
            float e1 = __expf(o1 - m);
            float inv = 1.0f / (e0 + e1);
            out[2 * b]     = e0 * inv;
            out[2 * b + 1] = e1 * inv;
        }
    };

    // ---- persistent loop over rows ----
    // Balanced split: warps 0-6 produce pairs 0..41 (6 pairs each);
    // warp 7 scans the previous row (~2000cyc) then produces pairs 42-44
    // (~2100cyc) -> all 8 warps ~equal, all 8 warps issue loads.
    int iter = 0;
    int b;
    for (b = blockIdx.x; b < B; b += gridDim.x, ++iter) {
        const int buf = iter & 1;
        const float4* xb = reinterpret_cast<const float4*>(x) + (size_t)b * 90 * 256;

        if (warp < 7) {
            #pragma unroll 2
            for (int p = warp; p < 42; p += 7) produce_pair(xb, 2 * p, buf);
        } else {
            if (iter > 0) scan_row(b - gridDim.x, buf ^ 1);
            produce_pair(xb, 84, buf);
            produce_pair(xb, 86, buf);
            produce_pair(xb, 88, buf);
        }
        __syncthreads();
    }

    // ---- epilogue: scan the final row ----
    if (iter > 0 && warp == 7) {
        scan_row(b - gridDim.x, (iter - 1) & 1);
    }
}

extern "C" void kernel_launch(void* const* d_in, const int* in_sizes, int n_in,
                              void* d_out, int out_size) {
    const float* x      = (const float*)d_in[0];
    const float* w_ant  = (const float*)d_in[1];
    const float* b_ant  = (const float*)d_in[2];
    const float* w_hid  = (const float*)d_in[3];
    const float* b_hid  = (const float*)d_in[4];
    const float* w_time = (const float*)d_in[5];
    const float* b_time = (const float*)d_in[6];
    const float* w_out  = (const float*)d_in[7];
    const float* b_out  = (const float*)d_in[8];
    float* out = (float*)d_out;

    const int B = in_sizes[0] / (90 * 4 * 256);   // 2048
    // occ-4: 148*4 = 592 CTAs, exactly 4 resident per SM, one wave.
    int grid = 592;
    if (grid > B) grid = B;
    snn_fused_kernel<<<grid, THREADS>>>(x, w_ant, b_ant, w_hid, b_hid,
                                        w_time, b_time, w_out, b_out, out, B);
}